// round 6
// baseline (speedup 1.0000x reference)
#include <cuda_runtime.h>

#define N_EMIT 512
#define ZPL    8
#define ROI    20
#define NPX    400
#define SPL_D  64
#define SPL_H  40
#define SPL_W  40
#define TPITCH 33

// One block = (echunk of 32 emitters) x (one z plane). 1024 threads = 32 warps.
// lane = emitter; warp w owns 13 (w<16) or 12 (w>=16) pixels.
__global__ __launch_bounds__(1024, 1) void psf_fused(
    const float* __restrict__ pos,
    const float* __restrict__ inten,
    const float* __restrict__ bg,
    const float* __restrict__ coefs,
    float* __restrict__ out)
{
    extern __shared__ float sval[];          // [NPX * TPITCH] transpose tile
    __shared__ float ssum[32][TPITCH];
    __shared__ float sscale[32];
    __shared__ float sbg[32];

    const int echunk = blockIdx.x & 15;
    const int z      = blockIdx.x >> 4;
    const int w      = threadIdx.x >> 5;
    const int lane   = threadIdx.x & 31;
    const int e      = echunk * 32 + lane;

    const float p0 = pos[e * 3 + 0];   // Y axis (faithful to reference)
    const float p1 = pos[e * 3 + 1];   // X axis
    const float p2 = pos[e * 3 + 2];   // Z axis

    // z terms (constant per thread)
    float pzf = (float)z - p2 + 28.0f;            // SPL_D/2 - ZPL/2
    float fz  = floorf(pzf);
    float dz  = pzf - fz;
    int   iz  = max(0, min((int)fz, SPL_D - 1));
    float dz2 = dz * dz, dz3 = dz2 * dz;
    const int izoff = iz * SPL_H;

    const int cnt    = (w < 16) ? 13 : 12;
    const int pstart = (w < 16) ? w * 13 : 208 + (w - 16) * 12;

    float nsum = 0.0f;

    #pragma unroll
    for (int i = 0; i < 13; i++) {
        if (i < cnt) {
            const int p = pstart + i;
            const int y = p / 20;
            const int x = p - y * 20;

            float pyf = (float)y - p0 + 10.0f;    // SPL_H/2 - ROI/2
            float fy  = floorf(pyf);
            float dy  = pyf - fy;
            int   iy  = max(0, min((int)fy, SPL_H - 1));

            float pxf = (float)x - p1 + 10.0f;    // SPL_W/2 - ROI/2
            float fx  = floorf(pxf);
            float dx  = pxf - fx;
            int   ix  = max(0, min((int)fx, SPL_W - 1));

            float dx2 = dx * dx, dx3 = dx2 * dx;
            float dy2 = dy * dy, dy3 = dy2 * dy;

            // Generically uniform address across the warp -> L1 broadcast.
            const float4* cp = (const float4*)(coefs +
                (((size_t)(izoff + iy) * SPL_W + ix) << 6));

            float s0, s1, s2, s3;
            {
                float4 c0 = cp[0], c1 = cp[1], c2 = cp[2], c3 = cp[3];
                float t0 = fmaf(c0.w, dx3, fmaf(c0.z, dx2, fmaf(c0.y, dx, c0.x)));
                float t1 = fmaf(c1.w, dx3, fmaf(c1.z, dx2, fmaf(c1.y, dx, c1.x)));
                float t2 = fmaf(c2.w, dx3, fmaf(c2.z, dx2, fmaf(c2.y, dx, c2.x)));
                float t3 = fmaf(c3.w, dx3, fmaf(c3.z, dx2, fmaf(c3.y, dx, c3.x)));
                s0 = fmaf(t3, dy3, fmaf(t2, dy2, fmaf(t1, dy, t0)));
            }
            {
                float4 c0 = cp[4], c1 = cp[5], c2 = cp[6], c3 = cp[7];
                float t0 = fmaf(c0.w, dx3, fmaf(c0.z, dx2, fmaf(c0.y, dx, c0.x)));
                float t1 = fmaf(c1.w, dx3, fmaf(c1.z, dx2, fmaf(c1.y, dx, c1.x)));
                float t2 = fmaf(c2.w, dx3, fmaf(c2.z, dx2, fmaf(c2.y, dx, c2.x)));
                float t3 = fmaf(c3.w, dx3, fmaf(c3.z, dx2, fmaf(c3.y, dx, c3.x)));
                s1 = fmaf(t3, dy3, fmaf(t2, dy2, fmaf(t1, dy, t0)));
            }
            {
                float4 c0 = cp[8], c1 = cp[9], c2 = cp[10], c3 = cp[11];
                float t0 = fmaf(c0.w, dx3, fmaf(c0.z, dx2, fmaf(c0.y, dx, c0.x)));
                float t1 = fmaf(c1.w, dx3, fmaf(c1.z, dx2, fmaf(c1.y, dx, c1.x)));
                float t2 = fmaf(c2.w, dx3, fmaf(c2.z, dx2, fmaf(c2.y, dx, c2.x)));
                float t3 = fmaf(c3.w, dx3, fmaf(c3.z, dx2, fmaf(c3.y, dx, c3.x)));
                s2 = fmaf(t3, dy3, fmaf(t2, dy2, fmaf(t1, dy, t0)));
            }
            {
                float4 c0 = cp[12], c1 = cp[13], c2 = cp[14], c3 = cp[15];
                float t0 = fmaf(c0.w, dx3, fmaf(c0.z, dx2, fmaf(c0.y, dx, c0.x)));
                float t1 = fmaf(c1.w, dx3, fmaf(c1.z, dx2, fmaf(c1.y, dx, c1.x)));
                float t2 = fmaf(c2.w, dx3, fmaf(c2.z, dx2, fmaf(c2.y, dx, c2.x)));
                float t3 = fmaf(c3.w, dx3, fmaf(c3.z, dx2, fmaf(c3.y, dx, c3.x)));
                s3 = fmaf(t3, dy3, fmaf(t2, dy2, fmaf(t1, dy, t0)));
            }
            float v = fmaf(s3, dz3, fmaf(s2, dz2, fmaf(s1, dz, s0)));

            sval[p * TPITCH + lane] = v;          // conflict-free STS, fire & forget
            nsum += v;
        }
    }

    // Per-emitter plane sums across 32 warps
    ssum[w][lane] = nsum;
    __syncthreads();
    if (w == 0) {
        float t = 0.0f;
        #pragma unroll
        for (int q = 0; q < 32; q++) t += ssum[q][lane];
        sscale[lane] = inten[e * ZPL + z] / t;
        sbg[lane]    = bg[e * ZPL + z];
    }
    __syncthreads();

    // warp w writes emitter w's 400 contiguous floats (stride-33 LDS, conflict-free)
    {
        const int   eo  = echunk * 32 + w;
        const float sc  = sscale[w];
        const float bgv = sbg[w];
        float* op = out + ((size_t)eo * ZPL + z) * NPX;
        #pragma unroll
        for (int m = 0; m < 13; m++) {
            int pp = m * 32 + lane;
            if (pp < NPX) op[pp] = fmaf(sval[pp * TPITCH + w], sc, bgv);
        }
    }
}

extern "C" void kernel_launch(void* const* d_in, const int* in_sizes, int n_in,
                              void* d_out, int out_size)
{
    const float* pos   = (const float*)d_in[0];
    const float* inten = (const float*)d_in[1];
    const float* bg    = (const float*)d_in[2];
    const float* coefs = (const float*)d_in[3];

    const int smem = NPX * TPITCH * sizeof(float);   // 52.8 KB dynamic
    cudaFuncSetAttribute(psf_fused, cudaFuncAttributeMaxDynamicSharedMemorySize, smem);
    psf_fused<<<128, 1024, smem>>>(pos, inten, bg, coefs, (float*)d_out);
}